// round 8
// baseline (speedup 1.0000x reference)
#include <cuda_runtime.h>
#include <cstdint>
#include <climits>

// ---------------- problem constants (match reference exactly) ----------------
#define BB   4
#define NPTS 300000
#define NC   5
#define GXX  432
#define GYY  496
#define GZZ  1
#define NVOX (GXX * GYY * GZZ)          // 214272 (divisible by 4)
#define MAXV 40000
#define MAXP 30
#define CAP  48                          // per-voxel index bucket capacity
#define CHUNK 1024
#define NB   ((NVOX + CHUNK - 1) / CHUNK)   // 210

#define FEATS_ELEMS ((size_t)BB * MAXV * MAXP * NC)   // 24,000,000 floats
#define F4_COORD ((BB * MAXV * 4) / 4)   // 160,000 float4

#define VALIDF (1 << 30)
#define ROWF   (MAXP * NC)               // 150 floats per feats row

// ---------------- static device scratch ----------------------------------------
__device__ int2 g_cell  [BB * NVOX];     // .x = count, .y = rank
__device__ int  g_agg   [BB * NB];
__device__ int  g_bucket[(size_t)BB * NVOX * CAP];

// ---------------- side stream: coords = -1 --------------------------------------
__global__ void k_coord(float4* __restrict__ coords4) {
    int i = blockIdx.x * blockDim.x + threadIdx.x;
    if (i < F4_COORD) coords4[i] = make_float4(-1.f, -1.f, -1.f, -1.f);
}

// ---------------- pass 1: voxelize + bucket append ----------------------------
__global__ void k_points(const float* __restrict__ pts) {
    int tid = blockIdx.x * blockDim.x + threadIdx.x;
    if (tid >= BB * NPTS) return;
    int b = tid / NPTS;
    int n = tid - b * NPTS;
    const float* p = pts + (size_t)tid * NC;
    float x = __ldg(p + 0), y = __ldg(p + 1), z = __ldg(p + 2);
    // identical float32 ops as reference: floor((p - lo) / vs)
    int ix = (int)floorf((x - 0.0f)   / 0.16f);
    int iy = (int)floorf((y + 39.68f) / 0.16f);
    int iz = (int)floorf((z + 3.0f)   / 4.0f);
    if (ix < 0 || ix >= GXX || iy < 0 || iy >= GYY || iz < 0 || iz >= GZZ) return;
    int vid = (iz * GYY + iy) * GXX + ix;
    int cell = b * NVOX + vid;
    int pos = atomicAdd(&g_cell[cell].x, 1);
    if (pos < CAP) g_bucket[(size_t)cell * CAP + pos] = n;
}

// ---------------- single-pass scan with decoupled lookback --------------------
// 840 blocks (256 thr) all fit in one wave on 148 SMs -> spin-wait is safe.
// Writes per-cell rank (g_cell[].y) AND the coords rows (coords = f(vid, rank)).
__global__ void k_scan(float* __restrict__ out) {
    int blk = blockIdx.x;
    int b  = blk / NB;
    int cb = blk - b * NB;
    int t  = threadIdx.x;
    __shared__ int sh[256];

    int base = cb * CHUNK + t * 4;           // multiple of 4; NVOX % 4 == 0
    int f0 = 0, f1 = 0, f2 = 0, f3 = 0;
    if (base < NVOX) {
        const int4* p4 = (const int4*)g_cell + ((size_t)(b * NVOX + base) >> 1);
        int4 q0 = __ldg(p4 + 0);             // cells base, base+1
        int4 q1 = __ldg(p4 + 1);             // cells base+2, base+3
        f0 = (q0.x > 0); f1 = (q0.z > 0);
        f2 = (q1.x > 0); f3 = (q1.z > 0);
    }
    int s = f0 + f1 + f2 + f3;
    sh[t] = s;
    __syncthreads();
    #pragma unroll
    for (int off = 1; off < 256; off <<= 1) {   // Hillis–Steele inclusive
        int v = (t >= off) ? sh[t - off] : 0;
        __syncthreads();
        sh[t] += v;
        __syncthreads();
    }
    int excl  = sh[t] - s;
    int total = sh[255];

    // publish this chunk's aggregate ASAP
    if (t == 0) atomicExch(&g_agg[blk], total | VALIDF);

    // lookback: sum all predecessor aggregates (within this batch)
    int partial = 0;
    for (int j = t; j < cb; j += 256) {
        int v;
        do { v = atomicAdd(&g_agg[b * NB + j], 0); } while (!(v & VALIDF));
        partial += (v & (VALIDF - 1));
    }
    __syncthreads();
    sh[t] = partial;
    __syncthreads();
    #pragma unroll
    for (int off = 128; off > 0; off >>= 1) {
        if (t < off) sh[t] += sh[t + off];
        __syncthreads();
    }
    int r = sh[0] + excl;

    float4* coords = (float4*)(out + FEATS_ELEMS);
    #pragma unroll
    for (int q = 0; q < 4; q++) {
        int f = (q == 0) ? f0 : (q == 1) ? f1 : (q == 2) ? f2 : f3;
        if (f) {
            int vid = base + q;
            g_cell[b * NVOX + vid].y = r;
            if (r < MAXV) {
                int izc = vid / (GXX * GYY);
                int rem = vid - izc * (GXX * GYY);
                coords[b * MAXV + r] = make_float4((float)b, (float)izc,
                                                   (float)(rem / GXX),
                                                   (float)(rem % GXX));
            }
            r++;
        }
    }
}

// ---------------- scatter: one thread per point --------------------------------
__global__ void k_scatter(const float* __restrict__ pts, float* __restrict__ out) {
    int tid = blockIdx.x * blockDim.x + threadIdx.x;
    if (tid >= BB * NPTS) return;
    int b = tid / NPTS;
    int n = tid - b * NPTS;
    const float* p = pts + (size_t)tid * NC;
    float x = __ldg(p + 0), y = __ldg(p + 1), z = __ldg(p + 2);
    int ix = (int)floorf((x - 0.0f)   / 0.16f);
    int iy = (int)floorf((y + 39.68f) / 0.16f);
    int iz = (int)floorf((z + 3.0f)   / 4.0f);
    if (ix < 0 || ix >= GXX || iy < 0 || iy >= GYY || iz < 0 || iz >= GZZ) return;
    int vid = (iz * GYY + iy) * GXX + ix;
    int cell = b * NVOX + vid;

    const int* bk = g_bucket + (size_t)cell * CAP;
    int2 ci = __ldg(&g_cell[cell]);           // {count, rank} — one 8B load
    int e0 = __ldg(bk + 0);                   // issue concurrently with ci
    int e1 = __ldg(bk + 1);
    int e2 = __ldg(bk + 2);
    int e3 = __ldg(bk + 3);

    if (ci.y >= MAXV) return;                 // voxel beyond unique cap
    int m = ci.x < CAP ? ci.x : CAP;

    int r = 0;
    bool found = false;
    if (m > 0) { r += (e0 < n); found |= (e0 == n); }
    if (m > 1) { r += (e1 < n); found |= (e1 == n); }
    if (m > 2) { r += (e2 < n); found |= (e2 == n); }
    if (m > 3) { r += (e3 < n); found |= (e3 == n); }
    for (int j = 4; j < m; j++) {
        int e = __ldg(bk + j);
        r += (e < n);
        found |= (e == n);
    }
    if (!found || r >= MAXP) return;          // overflow-dropped or beyond 30

    float* fo = out + ((size_t)(b * MAXV + ci.y)) * ROWF + r * NC;
    fo[0] = (x - 0.0f)   / 69.12f;
    fo[1] = (y + 39.68f) / 79.36f;
    fo[2] = (z + 3.0f)   / 4.0f;
    fo[3] = __ldg(p + 3);
    fo[4] = __ldg(p + 4);
}

// ---------------- launch: CE-overlapped graph -----------------------------------
//   main:  memset(cell) -> memset(agg) -> points ---------\
//   side:  memset(feats, 96MB, CE) -> coords(-1) ---------+--> scan -> scatter
extern "C" void kernel_launch(void* const* d_in, const int* in_sizes, int n_in,
                              void* d_out, int out_size) {
    const float* pts = (const float*)d_in[0];
    float* out = (float*)d_out;

    void* pcell = nullptr; cudaGetSymbolAddress(&pcell, g_cell);
    void* pagg  = nullptr; cudaGetSymbolAddress(&pagg,  g_agg);

    cudaStream_t side;
    cudaEvent_t eFork, eJoin;
    cudaStreamCreateWithFlags(&side, cudaStreamNonBlocking);
    cudaEventCreateWithFlags(&eFork, cudaEventDisableTiming);
    cudaEventCreateWithFlags(&eJoin, cudaEventDisableTiming);

    // fork: side stream zeroes the 96MB feats region (CE memset — no SM use)
    cudaEventRecord(eFork, 0);
    cudaStreamWaitEvent(side, eFork, 0);
    cudaMemsetAsync(out, 0, FEATS_ELEMS * sizeof(float), side);
    k_coord<<<(F4_COORD + 255) / 256, 256, 0, side>>>((float4*)(out + FEATS_ELEMS));
    cudaEventRecord(eJoin, side);

    // main chain
    cudaMemsetAsync(pcell, 0, sizeof(int2) * BB * NVOX);
    cudaMemsetAsync(pagg,  0, sizeof(int)  * BB * NB);
    k_points<<<(BB * NPTS + 255) / 256, 256>>>(pts);

    // join: scan writes coords rows; scatter writes into zeroed feats
    cudaStreamWaitEvent(0, eJoin, 0);
    k_scan   <<<BB * NB, 256>>>(out);
    k_scatter<<<(BB * NPTS + 255) / 256, 256>>>(pts, out);

    // NOTE: side/eFork/eJoin intentionally not destroyed — destroying objects
    // referenced by an in-progress capture is invalid; host-side only, no
    // device allocations, called a handful of times.
}